// round 6
// baseline (speedup 1.0000x reference)
#include <cuda_runtime.h>
#include <cuda_bf16.h>
#include <cstdint>

// Haar 3D wavelet transform, causal time pad (replicate first frame).
// x:  [B=2, C=3, T=33, H=512, W=512] fp32
// out:[B=2, 8*C=24, Tp=17, Hp=256, Wp=256] fp32, sub-band major (s*C + c)
//
// R6 (= R5 retry): compute in registers (R2 datapath), stage results in 32KB
// smem in global layout, then emit each sub-band's 4KB-contiguous CTA region
// as ONE cp.async.bulk shared->global transfer (UBLKCP) so DRAM sees large
// sequential write bursts instead of hash-ordered 128B evictions.

#define SCALE 0.3536f

static constexpr int B  = 2;
static constexpr int C  = 3;
static constexpr int T  = 33;
static constexpr int H  = 512;
static constexpr int W  = 512;
static constexpr int Tp = 17;
static constexpr int Hp = 256;
static constexpr int Wp = 256;
static constexpr int WP4 = Wp / 4;   // 64: each thread covers 4 wp = 2 input float4s

static constexpr int THREADS       = 256;
static constexpr int TOTAL_THREADS = B * C * Tp * Hp * WP4;      // 1,671,168 (= 6528 * 256)
static constexpr int OUT_CH_STRIDE = Tp * Hp * Wp;               // 1,114,112
static constexpr int IN_FRAME      = H * W;                      // 262,144
// Per CTA, per sub-band: 256 threads * 4 floats = 1024 floats = 4KB contiguous
static constexpr int SB_BYTES      = THREADS * 4 * 4;            // 4096

__global__ __launch_bounds__(THREADS)
void haar3d_kernel(const float* __restrict__ x, float* __restrict__ out) {
    __shared__ __align__(128) float stage[8][THREADS * 4];   // 32 KB

    int tid = threadIdx.x;
    int idx = blockIdx.x * THREADS + tid;

    int w8 = idx & (WP4 - 1);          // [0,64): pair-of-float4 index along W
    int r  = idx >> 6;
    int hp = r & (Hp - 1); r >>= 8;
    int tp = r % Tp;
    int rc = r / Tp;
    int c  = rc % C;
    int b  = rc / C;

    int t1 = 2 * tp;                     // xp[2tp+1] -> x[2tp]
    int t0 = (t1 == 0) ? 0 : (t1 - 1);   // xp[2tp]   -> x[2tp-1] (clamped)
    int h0 = 2 * hp;

    const int inBase = (b * C + c) * T * IN_FRAME;
    const float4* __restrict__ x4 = (const float4*)x;
    int r00 = (inBase + t0 * IN_FRAME + (h0    ) * W) / 4 + w8 * 2;
    int r01 = (inBase + t0 * IN_FRAME + (h0 + 1) * W) / 4 + w8 * 2;
    int r10 = (inBase + t1 * IN_FRAME + (h0    ) * W) / 4 + w8 * 2;
    int r11 = (inBase + t1 * IN_FRAME + (h0 + 1) * W) / 4 + w8 * 2;

    // 8 front-batched streaming loads
    float4 a00 = __ldcs(&x4[r00]);
    float4 a01 = __ldcs(&x4[r01]);
    float4 a10 = __ldcs(&x4[r10]);
    float4 a11 = __ldcs(&x4[r11]);
    float4 b00 = __ldcs(&x4[r00 + 1]);
    float4 b01 = __ldcs(&x4[r01 + 1]);
    float4 b10 = __ldcs(&x4[r10 + 1]);
    float4 b11 = __ldcs(&x4[r11 + 1]);

    float res[8][4];   // [sub-band][output wp lane]

    #pragma unroll
    for (int j = 0; j < 2; j++) {       // which input float4 (2 output lanes each)
        float4 v00 = j ? b00 : a00;
        float4 v01 = j ? b01 : a01;
        float4 v10 = j ? b10 : a10;
        float4 v11 = j ? b11 : a11;
        #pragma unroll
        for (int lane = 0; lane < 2; lane++) {
            float p000, p001, p010, p011, p100, p101, p110, p111;
            if (lane == 0) {
                p000 = v00.x; p001 = v00.y;
                p010 = v01.x; p011 = v01.y;
                p100 = v10.x; p101 = v10.y;
                p110 = v11.x; p111 = v11.y;
            } else {
                p000 = v00.z; p001 = v00.w;
                p010 = v01.z; p011 = v01.w;
                p100 = v10.z; p101 = v10.w;
                p110 = v11.z; p111 = v11.w;
            }
            int ol = j * 2 + lane;
            // W stage
            float w00s = p000 + p001, w00d = p000 - p001;
            float w01s = p010 + p011, w01d = p010 - p011;
            float w10s = p100 + p101, w10d = p100 - p101;
            float w11s = p110 + p111, w11d = p110 - p111;
            // H stage
            float h0ss = w00s + w01s, h0ds = w00s - w01s;
            float h0sd = w00d + w01d, h0dd = w00d - w01d;
            float h1ss = w10s + w11s, h1ds = w10s - w11s;
            float h1sd = w10d + w11d, h1dd = w10d - w11d;
            // T stage: s = st*4 + sh*2 + sw
            res[0][ol] = (h0ss + h1ss) * SCALE;
            res[1][ol] = (h0sd + h1sd) * SCALE;
            res[2][ol] = (h0ds + h1ds) * SCALE;
            res[3][ol] = (h0dd + h1dd) * SCALE;
            res[4][ol] = (h0ss - h1ss) * SCALE;
            res[5][ol] = (h0sd - h1sd) * SCALE;
            res[6][ol] = (h0ds - h1ds) * SCALE;
            res[7][ol] = (h0dd - h1dd) * SCALE;
        }
    }

    // Stage to smem in exact global order: within the CTA's 4KB region,
    // element offset = tid*4 (local_hp = tid>>6 covers 4 consecutive full rows).
    #pragma unroll
    for (int s = 0; s < 8; s++) {
        *(float4*)&stage[s][tid * 4] =
            make_float4(res[s][0], res[s][1], res[s][2], res[s][3]);
    }
    // Make generic-proxy STS visible to the async proxy, then sync the CTA.
    asm volatile("fence.proxy.async.shared::cta;" ::: "memory");
    __syncthreads();

    // Threads 0..7 each issue one 4KB bulk store (sub-band = tid).
    // For tid<8: idx>>6 == blockIdx*4, so (b,c,tp) match thread 0 and
    // hp == blockIdx*4 & 255 is already the CTA's first hp row.
    if (tid < 8) {
        int s = tid;
        int hp0 = hp & ~3;
        size_t gbase = ((size_t)(b * (8 * C) + s * C + c) * OUT_CH_STRIDE
                       + (size_t)(tp * Hp + hp0) * Wp);
        uint32_t saddr = (uint32_t)__cvta_generic_to_shared(&stage[s][0]);
        asm volatile(
            "cp.async.bulk.global.shared::cta.bulk_group [%0], [%1], %2;"
            :: "l"(out + gbase), "r"(saddr), "r"(SB_BYTES) : "memory");
        asm volatile("cp.async.bulk.commit_group;" ::: "memory");
        // smem must stay live until the bulk engine has READ it
        asm volatile("cp.async.bulk.wait_group.read 0;" ::: "memory");
    }
}

extern "C" void kernel_launch(void* const* d_in, const int* in_sizes, int n_in,
                              void* d_out, int out_size) {
    const float* x = (const float*)d_in[0];
    float* out = (float*)d_out;
    (void)in_sizes; (void)n_in; (void)out_size;

    const int blocks = TOTAL_THREADS / THREADS;   // exactly divisible: 6528
    haar3d_kernel<<<blocks, THREADS>>>(x, out);
}

// round 7
// speedup vs baseline: 1.1007x; 1.1007x over previous
#include <cuda_runtime.h>
#include <cuda_bf16.h>

// Haar 3D wavelet transform, causal time pad (replicate first frame).
// x:  [B=2, C=3, T=33, H=512, W=512] fp32
// out:[B=2, 8*C=24, Tp=17, Hp=256, Wp=256] fp32, sub-band major (s*C + c)
//
// R7: coarser per-thread tile. Each thread: 8 output wp positions
// (16 input floats along W) -> 16 front-batched LDG.128 streaming loads,
// then 16 STG.128 streaming stores (2 per sub-band). Longer same-direction
// DRAM bursts per warp to cut read/write turnaround.

#define SCALE 0.3536f

static constexpr int B  = 2;
static constexpr int C  = 3;
static constexpr int T  = 33;
static constexpr int H  = 512;
static constexpr int W  = 512;
static constexpr int Tp = 17;
static constexpr int Hp = 256;
static constexpr int Wp = 256;
static constexpr int WP8 = Wp / 8;   // 32: each thread covers 8 wp = 4 input float4s

static constexpr int TOTAL_THREADS = B * C * Tp * Hp * WP8;     // 835,584 (= 3264 * 256)
static constexpr int OUT_CH_STRIDE = Tp * Hp * Wp;               // 1,114,112
static constexpr int IN_FRAME      = H * W;                      // 262,144
static constexpr int SSTRIDE4      = (C * OUT_CH_STRIDE) / 4;    // float4 step per sub-band

__global__ __launch_bounds__(256)
void haar3d_kernel(const float* __restrict__ x, float* __restrict__ out) {
    int idx = blockIdx.x * blockDim.x + threadIdx.x;

    int w16 = idx & (WP8 - 1);         // [0,32): group of 4 float4s along W
    int r  = idx >> 5;
    int hp = r & (Hp - 1); r >>= 8;
    int tp = r % Tp;
    int rc = r / Tp;
    int c  = rc % C;
    int b  = rc / C;

    int t1 = 2 * tp;                     // xp[2tp+1] -> x[2tp]
    int t0 = (t1 == 0) ? 0 : (t1 - 1);   // xp[2tp]   -> x[2tp-1] (clamped)
    int h0 = 2 * hp;

    const int inBase = (b * C + c) * T * IN_FRAME;
    const float4* __restrict__ x4 = (const float4*)x;
    int r00 = (inBase + t0 * IN_FRAME + (h0    ) * W) / 4 + w16 * 4;
    int r01 = (inBase + t0 * IN_FRAME + (h0 + 1) * W) / 4 + w16 * 4;
    int r10 = (inBase + t1 * IN_FRAME + (h0    ) * W) / 4 + w16 * 4;
    int r11 = (inBase + t1 * IN_FRAME + (h0 + 1) * W) / 4 + w16 * 4;

    // 16 front-batched streaming loads: in[row][chunk]
    float4 in00[4], in01[4], in10[4], in11[4];
    #pragma unroll
    for (int j = 0; j < 4; j++) in00[j] = __ldcs(&x4[r00 + j]);
    #pragma unroll
    for (int j = 0; j < 4; j++) in01[j] = __ldcs(&x4[r01 + j]);
    #pragma unroll
    for (int j = 0; j < 4; j++) in10[j] = __ldcs(&x4[r10 + j]);
    #pragma unroll
    for (int j = 0; j < 4; j++) in11[j] = __ldcs(&x4[r11 + j]);

    // res4[s][half]: 8 sub-bands x 2 float4s (8 output wp lanes)
    float4 res4[8][2];

    #pragma unroll
    for (int j = 0; j < 4; j++) {       // input float4 j -> output lanes 2j, 2j+1
        float4 v00 = in00[j], v01 = in01[j], v10 = in10[j], v11 = in11[j];
        #pragma unroll
        for (int lane = 0; lane < 2; lane++) {
            float p000, p001, p010, p011, p100, p101, p110, p111;
            if (lane == 0) {
                p000 = v00.x; p001 = v00.y;
                p010 = v01.x; p011 = v01.y;
                p100 = v10.x; p101 = v10.y;
                p110 = v11.x; p111 = v11.y;
            } else {
                p000 = v00.z; p001 = v00.w;
                p010 = v01.z; p011 = v01.w;
                p100 = v10.z; p101 = v10.w;
                p110 = v11.z; p111 = v11.w;
            }
            int ol = j * 2 + lane;       // 0..7
            int half = ol >> 2;          // which float4
            int comp = ol & 3;           // which component
            // W stage
            float w00s = p000 + p001, w00d = p000 - p001;
            float w01s = p010 + p011, w01d = p010 - p011;
            float w10s = p100 + p101, w10d = p100 - p101;
            float w11s = p110 + p111, w11d = p110 - p111;
            // H stage
            float h0ss = w00s + w01s, h0ds = w00s - w01s;
            float h0sd = w00d + w01d, h0dd = w00d - w01d;
            float h1ss = w10s + w11s, h1ds = w10s - w11s;
            float h1sd = w10d + w11d, h1dd = w10d - w11d;
            // T stage: s = st*4 + sh*2 + sw
            float v[8];
            v[0] = (h0ss + h1ss) * SCALE;
            v[1] = (h0sd + h1sd) * SCALE;
            v[2] = (h0ds + h1ds) * SCALE;
            v[3] = (h0dd + h1dd) * SCALE;
            v[4] = (h0ss - h1ss) * SCALE;
            v[5] = (h0sd - h1sd) * SCALE;
            v[6] = (h0ds - h1ds) * SCALE;
            v[7] = (h0dd - h1dd) * SCALE;
            #pragma unroll
            for (int s = 0; s < 8; s++) {
                float* f = (float*)&res4[s][half];
                f[comp] = v[s];
            }
        }
    }

    // Output: channel = s*C + c ; two STG.128 per sub-band (8 consecutive wp)
    int wp = w16 * 8;
    int outBase4 = (((b * (8 * C)) + c) * OUT_CH_STRIDE
                   + (tp * Hp + hp) * Wp + wp) / 4;
    float4* __restrict__ o4 = (float4*)out;
    #pragma unroll
    for (int s = 0; s < 8; s++) {
        __stcs(&o4[outBase4 + s * SSTRIDE4    ], res4[s][0]);
        __stcs(&o4[outBase4 + s * SSTRIDE4 + 1], res4[s][1]);
    }
}

extern "C" void kernel_launch(void* const* d_in, const int* in_sizes, int n_in,
                              void* d_out, int out_size) {
    const float* x = (const float*)d_in[0];
    float* out = (float*)d_out;
    (void)in_sizes; (void)n_in; (void)out_size;

    const int threads = 256;
    const int blocks = TOTAL_THREADS / threads;   // exactly divisible: 3264
    haar3d_kernel<<<blocks, threads>>>(x, out);
}

// round 8
// speedup vs baseline: 1.2649x; 1.1492x over previous
#include <cuda_runtime.h>
#include <cuda_bf16.h>

// Haar 3D wavelet transform, causal time pad (replicate first frame).
// x:  [B=2, C=3, T=33, H=512, W=512] fp32
// out:[B=2, 8*C=24, Tp=17, Hp=256, Wp=256] fp32, sub-band major (s*C + c)
//
// Final: R2 datapath (best measured). Each thread: 4 output wp positions
// (8 input floats along W), 8x LDG.128 front-batched (__ldcg: L2-only),
// 8x STG.128 streaming stores (one per sub-band).

#define SCALE 0.3536f

static constexpr int B  = 2;
static constexpr int C  = 3;
static constexpr int T  = 33;
static constexpr int H  = 512;
static constexpr int W  = 512;
static constexpr int Tp = 17;
static constexpr int Hp = 256;
static constexpr int Wp = 256;
static constexpr int WP4 = Wp / 4;   // 64: each thread covers 4 wp = 2 input float4s

static constexpr int TOTAL_THREADS = B * C * Tp * Hp * WP4;     // 1,671,168 (= 6528 * 256)
static constexpr int OUT_CH_STRIDE = Tp * Hp * Wp;               // 1,114,112
static constexpr int IN_FRAME      = H * W;                      // 262,144
static constexpr int SSTRIDE4      = (C * OUT_CH_STRIDE) / 4;    // float4 step per sub-band

__global__ __launch_bounds__(256)
void haar3d_kernel(const float* __restrict__ x, float* __restrict__ out) {
    int idx = blockIdx.x * blockDim.x + threadIdx.x;

    int w8 = idx & (WP4 - 1);          // [0,64): pair-of-float4 index along W
    int r  = idx >> 6;
    int hp = r & (Hp - 1); r >>= 8;
    int tp = r % Tp;
    int rc = r / Tp;
    int c  = rc % C;
    int b  = rc / C;

    int t1 = 2 * tp;                     // xp[2tp+1] -> x[2tp]
    int t0 = (t1 == 0) ? 0 : (t1 - 1);   // xp[2tp]   -> x[2tp-1] (clamped)
    int h0 = 2 * hp;

    const int inBase = (b * C + c) * T * IN_FRAME;
    const float4* __restrict__ x4 = (const float4*)x;
    int r00 = (inBase + t0 * IN_FRAME + (h0    ) * W) / 4 + w8 * 2;
    int r01 = (inBase + t0 * IN_FRAME + (h0 + 1) * W) / 4 + w8 * 2;
    int r10 = (inBase + t1 * IN_FRAME + (h0    ) * W) / 4 + w8 * 2;
    int r11 = (inBase + t1 * IN_FRAME + (h0 + 1) * W) / 4 + w8 * 2;

    // 8 front-batched L2-only loads (touch-once stream; skip L1 allocation)
    float4 a00 = __ldcg(&x4[r00]);
    float4 a01 = __ldcg(&x4[r01]);
    float4 a10 = __ldcg(&x4[r10]);
    float4 a11 = __ldcg(&x4[r11]);
    float4 b00 = __ldcg(&x4[r00 + 1]);
    float4 b01 = __ldcg(&x4[r01 + 1]);
    float4 b10 = __ldcg(&x4[r10 + 1]);
    float4 b11 = __ldcg(&x4[r11 + 1]);

    float res[8][4];   // [sub-band][output wp lane]

    #pragma unroll
    for (int j = 0; j < 2; j++) {       // which input float4 (2 output lanes each)
        float4 v00 = j ? b00 : a00;
        float4 v01 = j ? b01 : a01;
        float4 v10 = j ? b10 : a10;
        float4 v11 = j ? b11 : a11;
        #pragma unroll
        for (int lane = 0; lane < 2; lane++) {
            float p000, p001, p010, p011, p100, p101, p110, p111;
            if (lane == 0) {
                p000 = v00.x; p001 = v00.y;
                p010 = v01.x; p011 = v01.y;
                p100 = v10.x; p101 = v10.y;
                p110 = v11.x; p111 = v11.y;
            } else {
                p000 = v00.z; p001 = v00.w;
                p010 = v01.z; p011 = v01.w;
                p100 = v10.z; p101 = v10.w;
                p110 = v11.z; p111 = v11.w;
            }
            int ol = j * 2 + lane;
            // W stage
            float w00s = p000 + p001, w00d = p000 - p001;
            float w01s = p010 + p011, w01d = p010 - p011;
            float w10s = p100 + p101, w10d = p100 - p101;
            float w11s = p110 + p111, w11d = p110 - p111;
            // H stage
            float h0ss = w00s + w01s, h0ds = w00s - w01s;
            float h0sd = w00d + w01d, h0dd = w00d - w01d;
            float h1ss = w10s + w11s, h1ds = w10s - w11s;
            float h1sd = w10d + w11d, h1dd = w10d - w11d;
            // T stage: s = st*4 + sh*2 + sw
            res[0][ol] = (h0ss + h1ss) * SCALE;
            res[1][ol] = (h0sd + h1sd) * SCALE;
            res[2][ol] = (h0ds + h1ds) * SCALE;
            res[3][ol] = (h0dd + h1dd) * SCALE;
            res[4][ol] = (h0ss - h1ss) * SCALE;
            res[5][ol] = (h0sd - h1sd) * SCALE;
            res[6][ol] = (h0ds - h1ds) * SCALE;
            res[7][ol] = (h0dd - h1dd) * SCALE;
        }
    }

    // Output: channel = s*C + c ; one STG.128 per sub-band
    int wp = w8 * 4;
    int outBase4 = (((b * (8 * C)) + c) * OUT_CH_STRIDE
                   + (tp * Hp + hp) * Wp + wp) / 4;
    float4* __restrict__ o4 = (float4*)out;
    #pragma unroll
    for (int s = 0; s < 8; s++) {
        __stcs(&o4[outBase4 + s * SSTRIDE4],
               make_float4(res[s][0], res[s][1], res[s][2], res[s][3]));
    }
}

extern "C" void kernel_launch(void* const* d_in, const int* in_sizes, int n_in,
                              void* d_out, int out_size) {
    const float* x = (const float*)d_in[0];
    float* out = (float*)d_out;
    (void)in_sizes; (void)n_in; (void)out_size;

    const int threads = 256;
    const int blocks = TOTAL_THREADS / threads;   // exactly divisible: 6528
    haar3d_kernel<<<blocks, threads>>>(x, out);
}

// round 9
// speedup vs baseline: 1.2936x; 1.0227x over previous
#include <cuda_runtime.h>
#include <cuda_bf16.h>

// Haar 3D wavelet transform, causal time pad (replicate first frame).
// x:  [B=2, C=3, T=33, H=512, W=512] fp32
// out:[B=2, 8*C=24, Tp=17, Hp=256, Wp=256] fp32, sub-band major (s*C + c)
//
// FINAL (= R2, best measured: 65.6us, 79.9% DRAM). Each thread: 4 output wp
// positions (8 input floats along W), 8x LDG.128 streaming (.cs) loads
// front-batched, 8x STG.128 streaming (.cs) stores (one per sub-band).

#define SCALE 0.3536f

static constexpr int B  = 2;
static constexpr int C  = 3;
static constexpr int T  = 33;
static constexpr int H  = 512;
static constexpr int W  = 512;
static constexpr int Tp = 17;
static constexpr int Hp = 256;
static constexpr int Wp = 256;
static constexpr int WP4 = Wp / 4;   // 64: each thread covers 4 wp = 2 input float4s

static constexpr int TOTAL_THREADS = B * C * Tp * Hp * WP4;     // 1,671,168 (= 6528 * 256)
static constexpr int OUT_CH_STRIDE = Tp * Hp * Wp;               // 1,114,112
static constexpr int IN_FRAME      = H * W;                      // 262,144
static constexpr int SSTRIDE4      = (C * OUT_CH_STRIDE) / 4;    // float4 step per sub-band

__global__ __launch_bounds__(256)
void haar3d_kernel(const float* __restrict__ x, float* __restrict__ out) {
    int idx = blockIdx.x * blockDim.x + threadIdx.x;
    if (idx >= TOTAL_THREADS) return;

    int w8 = idx & (WP4 - 1);          // [0,64): pair-of-float4 index along W
    int r  = idx >> 6;
    int hp = r & (Hp - 1); r >>= 8;
    int tp = r % Tp;
    int rc = r / Tp;
    int c  = rc % C;
    int b  = rc / C;

    int t1 = 2 * tp;                     // xp[2tp+1] -> x[2tp]
    int t0 = (t1 == 0) ? 0 : (t1 - 1);   // xp[2tp]   -> x[2tp-1] (clamped)
    int h0 = 2 * hp;

    const int inBase = (b * C + c) * T * IN_FRAME;
    const float4* __restrict__ x4 = (const float4*)x;
    int r00 = (inBase + t0 * IN_FRAME + (h0    ) * W) / 4 + w8 * 2;
    int r01 = (inBase + t0 * IN_FRAME + (h0 + 1) * W) / 4 + w8 * 2;
    int r10 = (inBase + t1 * IN_FRAME + (h0    ) * W) / 4 + w8 * 2;
    int r11 = (inBase + t1 * IN_FRAME + (h0 + 1) * W) / 4 + w8 * 2;

    // 8 front-batched streaming loads (MLP_p1 = 8)
    float4 a00 = __ldcs(&x4[r00]);
    float4 a01 = __ldcs(&x4[r01]);
    float4 a10 = __ldcs(&x4[r10]);
    float4 a11 = __ldcs(&x4[r11]);
    float4 b00 = __ldcs(&x4[r00 + 1]);
    float4 b01 = __ldcs(&x4[r01 + 1]);
    float4 b10 = __ldcs(&x4[r10 + 1]);
    float4 b11 = __ldcs(&x4[r11 + 1]);

    float res[8][4];   // [sub-band][output wp lane]

    #pragma unroll
    for (int j = 0; j < 2; j++) {       // which input float4 (2 output lanes each)
        float4 v00 = j ? b00 : a00;
        float4 v01 = j ? b01 : a01;
        float4 v10 = j ? b10 : a10;
        float4 v11 = j ? b11 : a11;
        #pragma unroll
        for (int lane = 0; lane < 2; lane++) {
            float p000, p001, p010, p011, p100, p101, p110, p111;
            if (lane == 0) {
                p000 = v00.x; p001 = v00.y;
                p010 = v01.x; p011 = v01.y;
                p100 = v10.x; p101 = v10.y;
                p110 = v11.x; p111 = v11.y;
            } else {
                p000 = v00.z; p001 = v00.w;
                p010 = v01.z; p011 = v01.w;
                p100 = v10.z; p101 = v10.w;
                p110 = v11.z; p111 = v11.w;
            }
            int ol = j * 2 + lane;
            // W stage
            float w00s = p000 + p001, w00d = p000 - p001;
            float w01s = p010 + p011, w01d = p010 - p011;
            float w10s = p100 + p101, w10d = p100 - p101;
            float w11s = p110 + p111, w11d = p110 - p111;
            // H stage
            float h0ss = w00s + w01s, h0ds = w00s - w01s;
            float h0sd = w00d + w01d, h0dd = w00d - w01d;
            float h1ss = w10s + w11s, h1ds = w10s - w11s;
            float h1sd = w10d + w11d, h1dd = w10d - w11d;
            // T stage: s = st*4 + sh*2 + sw
            res[0][ol] = (h0ss + h1ss) * SCALE;
            res[1][ol] = (h0sd + h1sd) * SCALE;
            res[2][ol] = (h0ds + h1ds) * SCALE;
            res[3][ol] = (h0dd + h1dd) * SCALE;
            res[4][ol] = (h0ss - h1ss) * SCALE;
            res[5][ol] = (h0sd - h1sd) * SCALE;
            res[6][ol] = (h0ds - h1ds) * SCALE;
            res[7][ol] = (h0dd - h1dd) * SCALE;
        }
    }

    // Output: channel = s*C + c ; one STG.128 per sub-band
    int wp = w8 * 4;
    int outBase4 = (((b * (8 * C)) + c) * OUT_CH_STRIDE
                   + (tp * Hp + hp) * Wp + wp) / 4;
    float4* __restrict__ o4 = (float4*)out;
    #pragma unroll
    for (int s = 0; s < 8; s++) {
        __stcs(&o4[outBase4 + s * SSTRIDE4],
               make_float4(res[s][0], res[s][1], res[s][2], res[s][3]));
    }
}

extern "C" void kernel_launch(void* const* d_in, const int* in_sizes, int n_in,
                              void* d_out, int out_size) {
    const float* x = (const float*)d_in[0];
    float* out = (float*)d_out;
    (void)in_sizes; (void)n_in; (void)out_size;

    const int threads = 256;
    const int blocks = (TOTAL_THREADS + threads - 1) / threads;
    haar3d_kernel<<<blocks, threads>>>(x, out);
}

// round 11
// speedup vs baseline: 1.3068x; 1.0102x over previous
#include <cuda_runtime.h>
#include <cuda_bf16.h>

// Haar 3D wavelet transform, causal time pad (replicate first frame).
// x:  [B=2, C=3, T=33, H=512, W=512] fp32
// out:[B=2, 8*C=24, Tp=17, Hp=256, Wp=256] fp32, sub-band major (s*C + c)
//
// FINAL (converged; verified twice at 65.6/66.3us harness, 58.7us kernel,
// ~79% DRAM = mixed-R/W scheduler ceiling for this pattern).
// Each thread: 4 output wp positions (8 input floats along W),
// 8x LDG.128 streaming (.cs) loads front-batched,
// 8x STG.128 streaming (.cs) stores (one per sub-band).

#define SCALE 0.3536f

static constexpr int B  = 2;
static constexpr int C  = 3;
static constexpr int T  = 33;
static constexpr int H  = 512;
static constexpr int W  = 512;
static constexpr int Tp = 17;
static constexpr int Hp = 256;
static constexpr int Wp = 256;
static constexpr int WP4 = Wp / 4;   // 64: each thread covers 4 wp = 2 input float4s

static constexpr int TOTAL_THREADS = B * C * Tp * Hp * WP4;     // 1,671,168 (= 6528 * 256)
static constexpr int OUT_CH_STRIDE = Tp * Hp * Wp;               // 1,114,112
static constexpr int IN_FRAME      = H * W;                      // 262,144
static constexpr int SSTRIDE4      = (C * OUT_CH_STRIDE) / 4;    // float4 step per sub-band

__global__ __launch_bounds__(256)
void haar3d_kernel(const float* __restrict__ x, float* __restrict__ out) {
    int idx = blockIdx.x * blockDim.x + threadIdx.x;
    if (idx >= TOTAL_THREADS) return;

    int w8 = idx & (WP4 - 1);          // [0,64): pair-of-float4 index along W
    int r  = idx >> 6;
    int hp = r & (Hp - 1); r >>= 8;
    int tp = r % Tp;
    int rc = r / Tp;
    int c  = rc % C;
    int b  = rc / C;

    int t1 = 2 * tp;                     // xp[2tp+1] -> x[2tp]
    int t0 = (t1 == 0) ? 0 : (t1 - 1);   // xp[2tp]   -> x[2tp-1] (clamped)
    int h0 = 2 * hp;

    const int inBase = (b * C + c) * T * IN_FRAME;
    const float4* __restrict__ x4 = (const float4*)x;
    int r00 = (inBase + t0 * IN_FRAME + (h0    ) * W) / 4 + w8 * 2;
    int r01 = (inBase + t0 * IN_FRAME + (h0 + 1) * W) / 4 + w8 * 2;
    int r10 = (inBase + t1 * IN_FRAME + (h0    ) * W) / 4 + w8 * 2;
    int r11 = (inBase + t1 * IN_FRAME + (h0 + 1) * W) / 4 + w8 * 2;

    // 8 front-batched streaming loads (MLP_p1 = 8)
    float4 a00 = __ldcs(&x4[r00]);
    float4 a01 = __ldcs(&x4[r01]);
    float4 a10 = __ldcs(&x4[r10]);
    float4 a11 = __ldcs(&x4[r11]);
    float4 b00 = __ldcs(&x4[r00 + 1]);
    float4 b01 = __ldcs(&x4[r01 + 1]);
    float4 b10 = __ldcs(&x4[r10 + 1]);
    float4 b11 = __ldcs(&x4[r11 + 1]);

    float res[8][4];   // [sub-band][output wp lane]

    #pragma unroll
    for (int j = 0; j < 2; j++) {       // which input float4 (2 output lanes each)
        float4 v00 = j ? b00 : a00;
        float4 v01 = j ? b01 : a01;
        float4 v10 = j ? b10 : a10;
        float4 v11 = j ? b11 : a11;
        #pragma unroll
        for (int lane = 0; lane < 2; lane++) {
            float p000, p001, p010, p011, p100, p101, p110, p111;
            if (lane == 0) {
                p000 = v00.x; p001 = v00.y;
                p010 = v01.x; p011 = v01.y;
                p100 = v10.x; p101 = v10.y;
                p110 = v11.x; p111 = v11.y;
            } else {
                p000 = v00.z; p001 = v00.w;
                p010 = v01.z; p011 = v01.w;
                p100 = v10.z; p101 = v10.w;
                p110 = v11.z; p111 = v11.w;
            }
            int ol = j * 2 + lane;
            // W stage
            float w00s = p000 + p001, w00d = p000 - p001;
            float w01s = p010 + p011, w01d = p010 - p011;
            float w10s = p100 + p101, w10d = p100 - p101;
            float w11s = p110 + p111, w11d = p110 - p111;
            // H stage
            float h0ss = w00s + w01s, h0ds = w00s - w01s;
            float h0sd = w00d + w01d, h0dd = w00d - w01d;
            float h1ss = w10s + w11s, h1ds = w10s - w11s;
            float h1sd = w10d + w11d, h1dd = w10d - w11d;
            // T stage: s = st*4 + sh*2 + sw
            res[0][ol] = (h0ss + h1ss) * SCALE;
            res[1][ol] = (h0sd + h1sd) * SCALE;
            res[2][ol] = (h0ds + h1ds) * SCALE;
            res[3][ol] = (h0dd + h1dd) * SCALE;
            res[4][ol] = (h0ss - h1ss) * SCALE;
            res[5][ol] = (h0sd - h1sd) * SCALE;
            res[6][ol] = (h0ds - h1ds) * SCALE;
            res[7][ol] = (h0dd - h1dd) * SCALE;
        }
    }

    // Output: channel = s*C + c ; one STG.128 per sub-band
    int wp = w8 * 4;
    int outBase4 = (((b * (8 * C)) + c) * OUT_CH_STRIDE
                   + (tp * Hp + hp) * Wp + wp) / 4;
    float4* __restrict__ o4 = (float4*)out;
    #pragma unroll
    for (int s = 0; s < 8; s++) {
        __stcs(&o4[outBase4 + s * SSTRIDE4],
               make_float4(res[s][0], res[s][1], res[s][2], res[s][3]));
    }
}

extern "C" void kernel_launch(void* const* d_in, const int* in_sizes, int n_in,
                              void* d_out, int out_size) {
    const float* x = (const float*)d_in[0];
    float* out = (float*)d_out;
    (void)in_sizes; (void)n_in; (void)out_size;

    const int threads = 256;
    const int blocks = (TOTAL_THREADS + threads - 1) / threads;
    haar3d_kernel<<<blocks, threads>>>(x, out);
}